// round 2
// baseline (speedup 1.0000x reference)
#include <cuda_runtime.h>
#include <cstdint>
#include <math.h>

#define BB 2
#define LL 256
#define HH 512
#define NHH 8
#define DHH 64
#define MM (BB*LL)   // 512

// ---------------- device scratch (no allocs allowed) ----------------
__device__ float g_qt [BB*NHH*LL*DHH];   // q_t[b,n,l,d]
__device__ float g_ktT[BB*NHH*DHH*LL];   // k transposed [b,n,d,l]
__device__ float g_vt [BB*NHH*LL*DHH];   // v_t[b,n,l,d]
__device__ float g_w2 [BB*LL*NHH*HH];    // W2[b,q,n,h]
__device__ float g_pre[BB*LL*HH];        // pre-output [b,q, n*64+d]

// ---------------- f32x2 helpers ----------------
__device__ __forceinline__ unsigned long long fma_f32x2(unsigned long long a,
                                                        unsigned long long b,
                                                        unsigned long long c) {
    unsigned long long d;
    asm("fma.rn.f32x2 %0, %1, %2, %3;" : "=l"(d) : "l"(a), "l"(b), "l"(c));
    return d;
}
__device__ __forceinline__ unsigned long long pack2(float x, float y) {
    unsigned long long r;
    asm("mov.b64 %0, {%1, %2};" : "=l"(r) : "f"(x), "f"(y));
    return r;
}
__device__ __forceinline__ float2 unpack2(unsigned long long v) {
    float2 r;
    asm("mov.b64 {%0, %1}, %2;" : "=f"(r.x), "=f"(r.y) : "l"(v));
    return r;
}

// ---------------- NT GEMM: C[m,c] = sum_k X[m,k]*W[c,k] + bias[c] ----------------
// z = 0: query@Wq -> g_qt     z = 1: key@Wk -> g_ktT (transposed)
// z = 2: value@Wv -> g_vt     z = 3: g_pre@Wf -> out_final
__global__ __launch_bounds__(256) void gemm_nt_kernel(
    int zbase,
    const float* __restrict__ key, const float* __restrict__ query, const float* __restrict__ value,
    const float* __restrict__ Wk, const float* __restrict__ bk,
    const float* __restrict__ Wq, const float* __restrict__ bq,
    const float* __restrict__ Wv, const float* __restrict__ bv,
    const float* __restrict__ Wf, const float* __restrict__ bf,
    float* __restrict__ out_final)
{
    int z = zbase + blockIdx.z;
    const float* X; const float* W; const float* bias;
    if (z == 0)      { X = query;  W = Wq; bias = bq; }
    else if (z == 1) { X = key;    W = Wk; bias = bk; }
    else if (z == 2) { X = value;  W = Wv; bias = bv; }
    else             { X = g_pre;  W = Wf; bias = bf; }

    __shared__ float As[16][68];
    __shared__ float Bs[16][68];

    int tid = threadIdx.x;
    int tx = tid & 15, ty = tid >> 4;      // tx -> n dir, ty -> m dir
    int m0 = blockIdx.y * 64, n0 = blockIdx.x * 64;
    int lrow = tid >> 2;                   // 0..63
    int lk4  = (tid & 3) * 4;              // 0,4,8,12

    float acc[4][4];
#pragma unroll
    for (int i = 0; i < 4; i++)
#pragma unroll
        for (int j = 0; j < 4; j++) acc[i][j] = 0.f;

    for (int ks = 0; ks < HH; ks += 16) {
        float4 a  = *(const float4*)&X[(m0 + lrow) * HH + ks + lk4];
        float4 wv = *(const float4*)&W[(n0 + lrow) * HH + ks + lk4];
        As[lk4 + 0][lrow] = a.x;  As[lk4 + 1][lrow] = a.y;
        As[lk4 + 2][lrow] = a.z;  As[lk4 + 3][lrow] = a.w;
        Bs[lk4 + 0][lrow] = wv.x; Bs[lk4 + 1][lrow] = wv.y;
        Bs[lk4 + 2][lrow] = wv.z; Bs[lk4 + 3][lrow] = wv.w;
        __syncthreads();
#pragma unroll
        for (int kk = 0; kk < 16; kk++) {
            float4 av  = *(const float4*)&As[kk][ty * 4];
            float4 bv4 = *(const float4*)&Bs[kk][tx * 4];
            acc[0][0] += av.x * bv4.x; acc[0][1] += av.x * bv4.y;
            acc[0][2] += av.x * bv4.z; acc[0][3] += av.x * bv4.w;
            acc[1][0] += av.y * bv4.x; acc[1][1] += av.y * bv4.y;
            acc[1][2] += av.y * bv4.z; acc[1][3] += av.y * bv4.w;
            acc[2][0] += av.z * bv4.x; acc[2][1] += av.z * bv4.y;
            acc[2][2] += av.z * bv4.z; acc[2][3] += av.z * bv4.w;
            acc[3][0] += av.w * bv4.x; acc[3][1] += av.w * bv4.y;
            acc[3][2] += av.w * bv4.z; acc[3][3] += av.w * bv4.w;
        }
        __syncthreads();
    }

#pragma unroll
    for (int i = 0; i < 4; i++) {
#pragma unroll
        for (int j = 0; j < 4; j++) {
            int m = m0 + ty * 4 + i;   // = b*256 + l
            int c = n0 + tx * 4 + j;   // = n*64 + d
            float v = acc[i][j] + bias[c];
            int b_ = m >> 8, l_ = m & 255, n_ = c >> 6, d_ = c & 63;
            if (z == 0)      g_qt [((b_ * NHH + n_) * LL + l_) * DHH + d_] = v;
            else if (z == 1) g_ktT[((b_ * NHH + n_) * DHH + d_) * LL + l_] = v;
            else if (z == 2) g_vt [((b_ * NHH + n_) * LL + l_) * DHH + d_] = v;
            else             out_final[m * HH + c] = v;
        }
    }
}

// ---------------- W2[b,q,n,h] = sum_d (q_t[b,n,q,d]+v_bias[n,d]) * Wr[n*64+d, h] ----------------
__global__ __launch_bounds__(256) void w2_kernel(const float* __restrict__ Wr,
                                                 const float* __restrict__ v_bias)
{
    int n  = blockIdx.z;
    int m0 = blockIdx.y * 64, h0 = blockIdx.x * 64;

    __shared__ float As[16][68];   // As[d_local][m]
    __shared__ float Bs[16][68];   // Bs[d_local][h]

    int tid = threadIdx.x;
    int tx = tid & 15, ty = tid >> 4;
    int lrow = tid >> 2, lk4 = (tid & 3) * 4;   // A loader: 64 m rows x 16 d
    int brow = tid >> 4, bh4 = (tid & 15) * 4;  // B loader: 16 d rows x 64 h

    float acc[4][4];
#pragma unroll
    for (int i = 0; i < 4; i++)
#pragma unroll
        for (int j = 0; j < 4; j++) acc[i][j] = 0.f;

    for (int ks = 0; ks < DHH; ks += 16) {
        int m = m0 + lrow; int b_ = m >> 8, q_ = m & 255;
        float4 a  = *(const float4*)&g_qt[((b_ * NHH + n) * LL + q_) * DHH + ks + lk4];
        float4 vb = *(const float4*)&v_bias[n * DHH + ks + lk4];
        a.x += vb.x; a.y += vb.y; a.z += vb.z; a.w += vb.w;
        As[lk4 + 0][lrow] = a.x; As[lk4 + 1][lrow] = a.y;
        As[lk4 + 2][lrow] = a.z; As[lk4 + 3][lrow] = a.w;

        float4 wv = *(const float4*)&Wr[(n * DHH + ks + brow) * HH + h0 + bh4];
        *(float4*)&Bs[brow][bh4] = wv;
        __syncthreads();
#pragma unroll
        for (int kk = 0; kk < 16; kk++) {
            float4 av  = *(const float4*)&As[kk][ty * 4];
            float4 bv4 = *(const float4*)&Bs[kk][tx * 4];
            acc[0][0] += av.x * bv4.x; acc[0][1] += av.x * bv4.y;
            acc[0][2] += av.x * bv4.z; acc[0][3] += av.x * bv4.w;
            acc[1][0] += av.y * bv4.x; acc[1][1] += av.y * bv4.y;
            acc[1][2] += av.y * bv4.z; acc[1][3] += av.y * bv4.w;
            acc[2][0] += av.z * bv4.x; acc[2][1] += av.z * bv4.y;
            acc[2][2] += av.z * bv4.z; acc[2][3] += av.z * bv4.w;
            acc[3][0] += av.w * bv4.x; acc[3][1] += av.w * bv4.y;
            acc[3][2] += av.w * bv4.z; acc[3][3] += av.w * bv4.w;
        }
        __syncthreads();
    }

#pragma unroll
    for (int i = 0; i < 4; i++) {
#pragma unroll
        for (int j = 0; j < 4; j++) {
            int m = m0 + ty * 4 + i;
            int h = h0 + tx * 4 + j;
            int b_ = m >> 8, q_ = m & 255;
            g_w2[((size_t)(b_ * LL + q_) * NHH + n) * HH + h] = acc[i][j];
        }
    }
}

// ---------------- fused attention: A_C + B_D + mask + softmax + attn@V ----------------
// one block per (b,q); 256 threads = 8 warps
__global__ __launch_bounds__(256, 1) void attn_kernel(
    const float* __restrict__ rel,
    const float* __restrict__ u_bias,
    const int*   __restrict__ seq_len,
    const int*   __restrict__ lex_num)
{
    int q = blockIdx.x, b = blockIdx.y;
    int tid = threadIdx.x;
    int w = tid >> 5, lane = tid & 31;

    __shared__ float squ[NHH][DHH];   // q + u_bias
    __shared__ float ss[NHH][LL];     // scores -> attn

    // phase 0: load q+u into smem
    {
        int i = tid * 2;                 // flat n*64+d, d even
        int n = i >> 6, d = i & 63;
        float2 t = *(const float2*)&g_qt[((b * NHH + n) * LL + q) * DHH + d];
        float2 u = *(const float2*)&u_bias[i];
        float* sp = &squ[0][0];
        sp[i]     = t.x + u.x;
        sp[i + 1] = t.y + u.y;
    }
    __syncthreads();

    // phase 1: A_C — warp w handles head n=w, lane owns 8 consecutive k
    {
        int n = w;
        float acck[8] = {0.f, 0.f, 0.f, 0.f, 0.f, 0.f, 0.f, 0.f};
        const float* ktp = g_ktT + (size_t)(b * NHH + n) * DHH * LL + lane * 8;
        const float* qup = squ[n];
#pragma unroll 4
        for (int d = 0; d < DHH; d++) {
            float qd = qup[d];
            float4 x0 = *(const float4*)&ktp[d * LL];
            float4 x1 = *(const float4*)&ktp[d * LL + 4];
            acck[0] += qd * x0.x; acck[1] += qd * x0.y;
            acck[2] += qd * x0.z; acck[3] += qd * x0.w;
            acck[4] += qd * x1.x; acck[5] += qd * x1.y;
            acck[6] += qd * x1.z; acck[7] += qd * x1.w;
        }
#pragma unroll
        for (int t = 0; t < 8; t++) ss[n][lane * 8 + t] = acck[t];
    }
    __syncthreads();

    // phase 2: B_D — warp w streams rel rows k = w*32 .. w*32+31
    {
        const float* w2p = g_w2 + (size_t)(b * LL + q) * NHH * HH;
        unsigned long long w2u[4][8][2];
#pragma unroll
        for (int j = 0; j < 4; j++) {
#pragma unroll
            for (int n = 0; n < 8; n++) {
                float4 t = *(const float4*)&w2p[n * HH + j * 128 + lane * 4];
                w2u[j][n][0] = pack2(t.x, t.y);
                w2u[j][n][1] = pack2(t.z, t.w);
            }
        }

        const float4* rp = (const float4*)(rel + (size_t)(b * LL + q) * LL * HH);
        int k0 = w * 32;
        float4 cur[4];
#pragma unroll
        for (int j = 0; j < 4; j++) cur[j] = rp[(size_t)k0 * 128 + j * 32 + lane];

        for (int r = 0; r < 32; r++) {
            int k  = k0 + r;
            int kn = (r < 31) ? (k + 1) : k;
            float4 nxt[4];
#pragma unroll
            for (int j = 0; j < 4; j++) nxt[j] = rp[(size_t)kn * 128 + j * 32 + lane];

            unsigned long long p[8];
#pragma unroll
            for (int n = 0; n < 8; n++) p[n] = 0ull;
#pragma unroll
            for (int j = 0; j < 4; j++) {
                unsigned long long rlo = pack2(cur[j].x, cur[j].y);
                unsigned long long rhi = pack2(cur[j].z, cur[j].w);
#pragma unroll
                for (int n = 0; n < 8; n++) {
                    p[n] = fma_f32x2(w2u[j][n][0], rlo, p[n]);
                    p[n] = fma_f32x2(w2u[j][n][1], rhi, p[n]);
                }
            }
            float red[8];
#pragma unroll
            for (int n = 0; n < 8; n++) {
                float2 t = unpack2(p[n]);
                red[n] = t.x + t.y;
            }
#pragma unroll
            for (int s = 16; s > 0; s >>= 1) {
#pragma unroll
                for (int n = 0; n < 8; n++)
                    red[n] += __shfl_xor_sync(0xffffffffu, red[n], s);
            }
            if (lane == 0) {
#pragma unroll
                for (int n = 0; n < 8; n++) ss[n][k] += red[n];
            }
#pragma unroll
            for (int j = 0; j < 4; j++) cur[j] = nxt[j];
        }
    }
    __syncthreads();

    // phase 3: scale + mask + softmax — warp w handles head n=w
    int total = seq_len[b] + lex_num[b];
    {
        int n = w;
        float v[8];
        float4 s0 = *(const float4*)&ss[n][lane * 8];
        float4 s1 = *(const float4*)&ss[n][lane * 8 + 4];
        v[0] = s0.x; v[1] = s0.y; v[2] = s0.z; v[3] = s0.w;
        v[4] = s1.x; v[5] = s1.y; v[6] = s1.z; v[7] = s1.w;
#pragma unroll
        for (int t = 0; t < 8; t++) {
            int kidx = lane * 8 + t;
            v[t] = (kidx < total) ? v[t] * 0.125f : -1e15f;
        }
        float mx = v[0];
#pragma unroll
        for (int t = 1; t < 8; t++) mx = fmaxf(mx, v[t]);
#pragma unroll
        for (int s = 16; s > 0; s >>= 1)
            mx = fmaxf(mx, __shfl_xor_sync(0xffffffffu, mx, s));
        float sum = 0.f;
#pragma unroll
        for (int t = 0; t < 8; t++) { v[t] = expf(v[t] - mx); sum += v[t]; }
#pragma unroll
        for (int s = 16; s > 0; s >>= 1)
            sum += __shfl_xor_sync(0xffffffffu, sum, s);
        float inv = 1.0f / sum;
#pragma unroll
        for (int t = 0; t < 8; t++) v[t] *= inv;
        *(float4*)&ss[n][lane * 8]     = make_float4(v[0], v[1], v[2], v[3]);
        *(float4*)&ss[n][lane * 8 + 4] = make_float4(v[4], v[5], v[6], v[7]);
        __syncwarp();
    }

    // phase 4: attn @ V — warp n, lane owns d = 2*lane, 2*lane+1
    {
        int n = w;
        const float* vp = g_vt + (size_t)(b * NHH + n) * LL * DHH + lane * 2;
        float ax = 0.f, ay = 0.f;
#pragma unroll 4
        for (int k = 0; k < LL; k++) {
            float a = ss[n][k];
            float2 vv = *(const float2*)&vp[k * DHH];
            ax += a * vv.x;
            ay += a * vv.y;
        }
        float* op = g_pre + (size_t)(b * LL + q) * HH + n * DHH + lane * 2;
        op[0] = ax;
        op[1] = ay;
    }
}

// ---------------- launch ----------------
extern "C" void kernel_launch(void* const* d_in, const int* in_sizes, int n_in,
                              void* d_out, int out_size) {
    (void)in_sizes; (void)n_in; (void)out_size;
    const float* key     = (const float*)d_in[0];
    const float* query   = (const float*)d_in[1];
    const float* value   = (const float*)d_in[2];
    const float* rel     = (const float*)d_in[3];
    const float* Wk      = (const float*)d_in[4];
    const float* bk      = (const float*)d_in[5];
    const float* Wq      = (const float*)d_in[6];
    const float* bq      = (const float*)d_in[7];
    const float* Wv      = (const float*)d_in[8];
    const float* bv      = (const float*)d_in[9];
    const float* Wr      = (const float*)d_in[10];
    // d_in[11] = br: additive constant per (b,n,q) row of scores -> cancels in softmax
    const float* u_bias  = (const float*)d_in[12];
    const float* v_bias  = (const float*)d_in[13];
    const float* Wf      = (const float*)d_in[14];
    const float* bf      = (const float*)d_in[15];
    const int*   seq_len = (const int*)d_in[16];
    const int*   lex_num = (const int*)d_in[17];
    float* out = (float*)d_out;

    dim3 g1(8, 8, 3);
    gemm_nt_kernel<<<g1, 256>>>(0, key, query, value, Wk, bk, Wq, bq, Wv, bv, Wf, bf, out);

    dim3 g2(8, 8, NHH);
    w2_kernel<<<g2, 256>>>(Wr, v_bias);

    dim3 g3(LL, BB);
    attn_kernel<<<g3, 256>>>(rel, u_bias, seq_len, lex_num);

    dim3 g4(8, 8, 1);
    gemm_nt_kernel<<<g4, 256>>>(3, key, query, value, Wk, bk, Wq, bq, Wv, bv, Wf, bf, out);
}